// round 14
// baseline (speedup 1.0000x reference)
#include <cuda_runtime.h>
#include <cuda_pipeline.h>
#include <cuda_fp16.h>
#include <cstdint>

#define N_NODES 32768
#define EMB 128
#define N_CODES 4096
#define NG 512

// output layout: c_logit[512], c_graph[512*128], s_graph[512*128],
// loss_c, loss_s, c_node[32768*128], s_node[32768*128]
#define OFF_LOGIT 0
#define OFF_CG    512
#define OFF_SG    (512 + 65536)
#define OFF_LC    (512 + 2 * 65536)
#define OFF_LS    (OFF_LC + 1)
#define OFF_CN    (OFF_LS + 1)
#define OFF_SN    (OFF_CN + N_NODES * EMB)

// device scratch (no allocations allowed)
__device__ __align__(16) unsigned short g_Bh[8192 * 128];  // fp16 codebook [n][k]
__device__ __align__(16) float g_halfc2[8192];             // 0.5*|c_n|^2 exact fp32
__device__ int g_candc[N_NODES * 12];                      // 12 candidates/node (cb c)
__device__ int g_cands[N_NODES * 12];                      // 12 candidates/node (cb s)
__device__ int g_idxc[N_NODES], g_idxs[N_NODES];           // final exact indices
__device__ int g_counts[NG];
__device__ double g_loss[2];

// ---------------- helpers ----------------
__device__ __forceinline__ uint32_t smem_u32(const void* p) {
    uint32_t a;
    asm("{ .reg .u64 t; cvta.to.shared.u64 t, %1; cvt.u32.u64 %0, t; }" : "=r"(a) : "l"(p));
    return a;
}
// pack two floats to fp16x2: lo 16 bits = a, hi = b
__device__ __forceinline__ uint32_t pack_f16x2(float a, float b) {
    uint32_t r;
    asm("cvt.rn.f16x2.f32 %0, %1, %2;" : "=r"(r) : "f"(b), "f"(a));
    return r;
}
// fp16 in, fp16 accumulate: 2-reg C fragment
__device__ __forceinline__ void mma_f16(uint32_t* c, const uint32_t* a, uint32_t b0, uint32_t b1) {
    asm volatile(
        "mma.sync.aligned.m16n8k16.row.col.f16.f16.f16.f16 "
        "{%0,%1}, {%2,%3,%4,%5}, {%6,%7}, {%0,%1};"
        : "+r"(c[0]), "+r"(c[1])
        : "r"(a[0]), "r"(a[1]), "r"(a[2]), "r"(a[3]), "r"(b0), "r"(b1));
}
__device__ __forceinline__ void ldm4(uint32_t* r, uint32_t addr) {
    asm volatile("ldmatrix.sync.aligned.m8n8.x4.shared.b16 {%0,%1,%2,%3}, [%4];"
                 : "=r"(r[0]), "=r"(r[1]), "=r"(r[2]), "=r"(r[3]) : "r"(addr));
}
// top-3 (smallest) tracker, approx phase (tie-break irrelevant: exact rescore later)
__device__ __forceinline__ void upd3(float d, int idx, float (&bd)[3], int (&bi)[3]) {
    if (d < bd[2]) {
        if (d < bd[1]) {
            if (d < bd[0]) {
                bd[2] = bd[1]; bi[2] = bi[1];
                bd[1] = bd[0]; bi[1] = bi[0];
                bd[0] = d;     bi[0] = idx;
            } else {
                bd[2] = bd[1]; bi[2] = bi[1];
                bd[1] = d;     bi[1] = idx;
            }
        } else { bd[2] = d; bi[2] = idx; }
    }
}

// ---------- B prep (fused with init): fp16 pack + 0.5|c|^2 ----------
__global__ void bprep_kernel(const float* __restrict__ cbc, const float* __restrict__ cbs,
                             float* __restrict__ out) {
    // fused init: blocks 0-255 zero CG/SG region, counts, losses
    if (blockIdx.x < 256) {
        int i = blockIdx.x * 256 + threadIdx.x;   // 0..65535
        if (i < NG) g_counts[i] = 0;
        if (i < 2) g_loss[i] = 0.0;
        out[OFF_CG + 2 * i] = 0.f;
        out[OFF_CG + 2 * i + 1] = 0.f;
    }
    int row = blockIdx.x * 8 + (threadIdx.x >> 5);
    int lane = threadIdx.x & 31;
    const float* src = (row < N_CODES) ? cbc + (size_t)row * EMB
                                       : cbs + (size_t)(row - N_CODES) * EMB;
    float4 v = ((const float4*)src)[lane];
    float ss = v.x * v.x + v.y * v.y + v.z * v.z + v.w * v.w;
    uint32_t* hid = (uint32_t*)g_Bh;
    hid[row * 64 + lane * 2] = pack_f16x2(v.x, v.y);
    hid[row * 64 + lane * 2 + 1] = pack_f16x2(v.z, v.w);
    for (int o = 16; o; o >>= 1) ss += __shfl_xor_sync(0xffffffffu, ss, o);
    if (lane == 0) g_halfc2[row] = 0.5f * ss;
}

// ---------- tensor GEMM (fp16 in / fp16 accum) + per-thread top-3 ----------
// grid 256 CTAs x 256 threads; each CTA owns 128 m-rows, scans 8192 codes
// in 128 chunks of 64. B double-buffered fp16 in smem, ldmatrix loads.
#define BSTRIDE 272
#define BUFB 17408                       // 64 rows * 272B
#define SMEM_GEMM (2 * BUFB + 512)       // 2x B + 2x256B halfc2

__device__ __forceinline__ void prefetch(char* smem, int ci, int tid) {
    int buf = ci & 1;
    int nb = ci * 64;
    char* hid = smem + buf * BUFB;
#pragma unroll
    for (int i = 0; i < 4; i++) {
        int idx = tid + i * 256;                 // 0..1023
        int row = idx >> 4, seg = idx & 15;
        __pipeline_memcpy_async(hid + row * BSTRIDE + seg * 16,
                                (const char*)g_Bh + (size_t)(nb + row) * 256 + seg * 16, 16);
    }
    if (tid < 16)
        __pipeline_memcpy_async(smem + 2 * BUFB + (ci & 1) * 256 + tid * 16,
                                (const char*)g_halfc2 + (size_t)nb * 4 + tid * 16, 16);
}

template <int CB>
__device__ __forceinline__ void half_loop(
    char* smem, uint32_t smemBase, uint32_t rp, int tid, int c,
    const uint32_t (&Ah)[8][4], float g0, float g1,
    float (&d0)[3], int (&i0)[3], float (&d1)[3], int (&i1)[3]) {
    for (int i = 0; i < 64; i++) {
        int ci = CB * 64 + i;
        __pipeline_wait_prior(0);
        __syncthreads();
        if (ci + 1 < 128) { prefetch(smem, ci + 1, tid); __pipeline_commit(); }
        int buf = ci & 1;
        uint32_t hiB = smemBase + buf * BUFB + rp;
        const float* h2 = (const float*)(smem + 2 * BUFB + buf * 256);
        uint32_t acc[8][2];
#pragma unroll
        for (int t = 0; t < 8; t++) { acc[t][0] = 0u; acc[t][1] = 0u; }  // fp16 +0 pairs
#pragma unroll
        for (int kt = 0; kt < 8; kt++) {
            uint32_t BH[4][4];
#pragma unroll
            for (int j = 0; j < 4; j++)
                ldm4(BH[j], hiB + j * (16 * BSTRIDE) + kt * 32);
#pragma unroll
            for (int t = 0; t < 8; t++)
                mma_f16(acc[t], Ah[kt],
                        BH[t >> 1][(t & 1) * 2], BH[t >> 1][(t & 1) * 2 + 1]);
        }
#pragma unroll
        for (int t = 0; t < 8; t++) {
            float2 hh = *(const float2*)(h2 + t * 8 + 2 * c);
            int col = i * 64 + t * 8 + 2 * c;       // local codebook index 0..4095
            __half2 p0 = *reinterpret_cast<const __half2*>(&acc[t][0]);
            __half2 p1 = *reinterpret_cast<const __half2*>(&acc[t][1]);
            float a0 = __low2float(p0), a1 = __high2float(p0);
            float a2 = __low2float(p1), a3 = __high2float(p1);
            upd3(fmaf(-g0, a0, hh.x), col, d0, i0);
            upd3(fmaf(-g0, a1, hh.y), col + 1, d0, i0);
            upd3(fmaf(-g1, a2, hh.x), col, d1, i1);
            upd3(fmaf(-g1, a3, hh.y), col + 1, d1, i1);
        }
    }
}

__global__ void __launch_bounds__(256)
gemm_argmin_kernel(const float* __restrict__ nodef, const float* __restrict__ score) {
    extern __shared__ char smem[];
    const int tid = threadIdx.x;
    const int w = tid >> 5, lane = tid & 31;
    const int gp = lane >> 2, c = lane & 3;
    const int mbase = blockIdx.x * 128;
    const int r0 = mbase + w * 16 + gp, r1 = r0 + 8;

    prefetch(smem, 0, tid);
    __pipeline_commit();

    // A fragments (fp16), loaded once per CTA
    uint32_t Ah[8][4];
#pragma unroll
    for (int kt = 0; kt < 8; kt++) {
        const float* p0 = nodef + (size_t)r0 * EMB + kt * 16 + 2 * c;
        const float* p1 = nodef + (size_t)r1 * EMB + kt * 16 + 2 * c;
        float2 v;
        v = *(const float2*)p0;       Ah[kt][0] = pack_f16x2(v.x, v.y);
        v = *(const float2*)p1;       Ah[kt][1] = pack_f16x2(v.x, v.y);
        v = *(const float2*)(p0 + 8); Ah[kt][2] = pack_f16x2(v.x, v.y);
        v = *(const float2*)(p1 + 8); Ah[kt][3] = pack_f16x2(v.x, v.y);
    }

    float s0 = score[r0], s1 = score[r1];
    float gc0 = 0.5f + 0.5f * s0, gc1 = 0.5f + 0.5f * s1;
    float gs0 = 1.0f - 0.5f * s0, gs1 = 1.0f - 0.5f * s1;

    // ldmatrix per-thread row address part
    int g8 = lane >> 3, rr = lane & 7;
    uint32_t rp = (uint32_t)((8 * (g8 >> 1) + rr) * BSTRIDE + (g8 & 1) * 16);
    uint32_t smemBase = smem_u32(smem);

    const float INF = __int_as_float(0x7f800000);
    float dC0[3] = {INF, INF, INF}, dC1[3] = {INF, INF, INF};
    float dS0[3] = {INF, INF, INF}, dS1[3] = {INF, INF, INF};
    int iC0[3] = {0, 0, 0}, iC1[3] = {0, 0, 0}, iS0[3] = {0, 0, 0}, iS1[3] = {0, 0, 0};

    half_loop<0>(smem, smemBase, rp, tid, c, Ah, gc0, gc1, dC0, iC0, dC1, iC1);
    half_loop<1>(smem, smemBase, rp, tid, c, Ah, gs0, gs1, dS0, iS0, dS1, iS1);

    // each thread writes its 3 candidates per row per codebook (12 total per row/cb)
    int b0 = r0 * 12 + c * 3, b1 = r1 * 12 + c * 3;
#pragma unroll
    for (int j = 0; j < 3; j++) {
        g_candc[b0 + j] = iC0[j];
        g_candc[b1 + j] = iC1[j];
        g_cands[b0 + j] = iS0[j];
        g_cands[b1 + j] = iS1[j];
    }
}

// ---------- exact fp32 rescore of 12 candidates (batched loads + ILP reduce) ----------
__global__ void __launch_bounds__(64)
rescore_kernel(const float* __restrict__ nodef, const float* __restrict__ score,
               const float* __restrict__ cbc, const float* __restrict__ cbs) {
    int n = blockIdx.x;
    int wid = threadIdx.x >> 5, lane = threadIdx.x & 31;
    const int* cand = (wid ? g_cands : g_candc) + n * 12;
    const float* cb = wid ? cbs : cbc;
    const float* h2 = g_halfc2 + (wid ? 4096 : 0);
    float4 x = ((const float4*)(nodef + (size_t)n * EMB))[lane];

    int idx[12];
#pragma unroll
    for (int j = 0; j < 12; j++) idx[j] = cand[j];

    float4 av[12];
#pragma unroll
    for (int j = 0; j < 12; j++)
        av[j] = ((const float4*)(cb + (size_t)idx[j] * EMB))[lane];

    float pd[12];
#pragma unroll
    for (int j = 0; j < 12; j++)
        pd[j] = x.x * av[j].x + x.y * av[j].y + x.z * av[j].z + x.w * av[j].w;

#pragma unroll
    for (int o = 16; o; o >>= 1) {
#pragma unroll
        for (int j = 0; j < 12; j++)
            pd[j] += __shfl_xor_sync(0xffffffffu, pd[j], o);
    }

    if (lane == 0) {
        float s = score[n];
        float g = wid ? (1.0f - 0.5f * s) : (0.5f + 0.5f * s);
        float bestd = __int_as_float(0x7f800000);
        int besti = 0x7fffffff;
#pragma unroll
        for (int j = 0; j < 12; j++) {
            float D = fmaf(-g, pd[j], h2[idx[j]]);
            if (D < bestd || (D == bestd && idx[j] < besti)) { bestd = D; besti = idx[j]; }
        }
        if (wid) g_idxs[n] = besti; else g_idxc[n] = besti;
    }
}

// ---------- per-node outputs + segment sums + commit losses (fp32 accum) ----------
__global__ void __launch_bounds__(128)
node_kernel(const float* __restrict__ nodef, const float* __restrict__ score,
            const int* __restrict__ batch,
            const float* __restrict__ cbc, const float* __restrict__ cbs,
            float* __restrict__ out) {
    __shared__ float s_sh[32];
    __shared__ int b_sh[32], ic_sh[32], is_sh[32];
    __shared__ float lred[8];
    const int tid = threadIdx.x;
    const int n0 = blockIdx.x * 32;
    if (tid < 32) {
        int n = n0 + tid;
        s_sh[tid] = score[n];
        b_sh[tid] = batch[n];
        ic_sh[tid] = g_idxc[n];
        is_sh[tid] = g_idxs[n];
    }
    __syncthreads();
    float* csum = out + OFF_CG;
    float* ssum = out + OFF_SG;
    float* cn = out + OFF_CN;
    float* sn = out + OFF_SN;
    const int d = tid;
    float cacc = 0.f, sacc = 0.f;
    float lc = 0.f, ls = 0.f;
    int curg = b_sh[0], runlen = 0;
    for (int ii = 0; ii < 32; ii += 4) {
        float xv[4], qcv[4], qsv[4];
#pragma unroll
        for (int u = 0; u < 4; u++) {
            int n = n0 + ii + u;
            xv[u] = nodef[(size_t)n * EMB + d];
            qcv[u] = cbc[(size_t)ic_sh[ii + u] * EMB + d];
            qsv[u] = cbs[(size_t)is_sh[ii + u] * EMB + d];
        }
#pragma unroll
        for (int u = 0; u < 4; u++) {
            int i = ii + u;
            int n = n0 + i;
            int gidx = b_sh[i];
            if (gidx != curg) {
                atomicAdd(&csum[curg * EMB + d], cacc);
                atomicAdd(&ssum[curg * EMB + d], sacc);
                if (d == 0) atomicAdd(&g_counts[curg], runlen);
                cacc = 0.f; sacc = 0.f; runlen = 0; curg = gidx;
            }
            float x = xv[u];
            float s = s_sh[i];
            float qc = qcv[u];
            float qs = qsv[u];
            float cv = x * s + qc;
            float sv = x * (1.f - s) + qs;
            cn[(size_t)n * EMB + d] = cv;
            sn[(size_t)n * EMB + d] = sv;
            float dc = qc - (0.5f + 0.5f * s) * x;
            float ds = qs - (1.0f - 0.5f * s) * x;
            lc = fmaf(dc, dc, lc);
            ls = fmaf(ds, ds, ls);
            cacc += cv; sacc += sv; runlen++;
        }
    }
    atomicAdd(&csum[curg * EMB + d], cacc);
    atomicAdd(&ssum[curg * EMB + d], sacc);
    if (d == 0) atomicAdd(&g_counts[curg], runlen);
    for (int o = 16; o; o >>= 1) {
        lc += __shfl_xor_sync(0xffffffffu, lc, o);
        ls += __shfl_xor_sync(0xffffffffu, ls, o);
    }
    int w = tid >> 5, lane = tid & 31;
    if (lane == 0) { lred[w] = lc; lred[4 + w] = ls; }
    __syncthreads();
    if (tid == 0) {
        atomicAdd(&g_loss[0], (double)(lred[0] + lred[1] + lred[2] + lred[3]));
        atomicAdd(&g_loss[1], (double)(lred[4] + lred[5] + lred[6] + lred[7]));
    }
}

// ---------- fused finalize (means + losses) + classifier head ----------
__global__ void __launch_bounds__(256)
head_kernel(const float* __restrict__ w1, const float* __restrict__ b1,
            const float* __restrict__ gamma, const float* __restrict__ beta,
            const float* __restrict__ rmean, const float* __restrict__ rvar,
            const float* __restrict__ w2, const float* __restrict__ b2,
            float* __restrict__ out) {
    __shared__ float cg_s[128];
    __shared__ float red[256];
    int g = blockIdx.x, j = threadIdx.x;
    if (j < 128) {
        float cnt = fmaxf((float)g_counts[g], 1.0f);
        float cgv = out[OFF_CG + g * EMB + j] / cnt;
        out[OFF_CG + g * EMB + j] = cgv;
        out[OFF_SG + g * EMB + j] = out[OFF_SG + g * EMB + j] / cnt;
        cg_s[j] = cgv;
    }
    if (g == 0 && j == 0) {
        out[OFF_LC] = (float)(g_loss[0] / ((double)N_NODES * (double)EMB));
        out[OFF_LS] = (float)(g_loss[1] / ((double)N_NODES * (double)EMB));
    }
    __syncthreads();
    float acc = 0.f;
#pragma unroll 8
    for (int k = 0; k < 128; k++) acc = fmaf(cg_s[k], w1[k * 256 + j], acc);
    float h = acc + b1[j];
    h = (h - rmean[j]) * rsqrtf(rvar[j] + 1e-5f) * gamma[j] + beta[j];
    h = fmaxf(h, 0.f);
    red[j] = h * w2[j];
    __syncthreads();
    for (int o = 128; o; o >>= 1) {
        if (j < o) red[j] += red[j + o];
        __syncthreads();
    }
    if (j == 0) out[OFF_LOGIT + g] = red[0] + b2[0];
}

extern "C" void kernel_launch(void* const* d_in, const int* in_sizes, int n_in,
                              void* d_out, int out_size) {
    (void)in_sizes; (void)n_in; (void)out_size;
    const float* nodef = (const float*)d_in[0];
    const float* score = (const float*)d_in[1];
    const int* batch = (const int*)d_in[2];
    const float* cbc = (const float*)d_in[3];
    const float* cbs = (const float*)d_in[4];
    const float* w1 = (const float*)d_in[5];
    const float* b1 = (const float*)d_in[6];
    const float* gamma = (const float*)d_in[7];
    const float* beta = (const float*)d_in[8];
    const float* rmean = (const float*)d_in[9];
    const float* rvar = (const float*)d_in[10];
    const float* w2 = (const float*)d_in[11];
    const float* b2 = (const float*)d_in[12];
    float* out = (float*)d_out;

    cudaFuncSetAttribute(gemm_argmin_kernel,
                         cudaFuncAttributeMaxDynamicSharedMemorySize, SMEM_GEMM);

    bprep_kernel<<<1024, 256>>>(cbc, cbs, out);
    gemm_argmin_kernel<<<256, 256, SMEM_GEMM>>>(nodef, score);
    rescore_kernel<<<N_NODES, 64>>>(nodef, score, cbc, cbs);
    node_kernel<<<1024, 128>>>(nodef, score, batch, cbc, cbs, out);
    head_kernel<<<NG, 256>>>(w1, b1, gamma, beta, rmean, rvar, w2, b2, out);
}

// round 15
// speedup vs baseline: 1.6267x; 1.6267x over previous
#include <cuda_runtime.h>
#include <cuda_pipeline.h>
#include <cuda_bf16.h>
#include <cstdint>

#define N_NODES 32768
#define EMB 128
#define N_CODES 4096
#define NG 512

// output layout: c_logit[512], c_graph[512*128], s_graph[512*128],
// loss_c, loss_s, c_node[32768*128], s_node[32768*128]
#define OFF_LOGIT 0
#define OFF_CG    512
#define OFF_SG    (512 + 65536)
#define OFF_LC    (512 + 2 * 65536)
#define OFF_LS    (OFF_LC + 1)
#define OFF_CN    (OFF_LS + 1)
#define OFF_SN    (OFF_CN + N_NODES * EMB)

// device scratch (no allocations allowed)
__device__ __align__(16) __nv_bfloat16 g_Bhi[8192 * 128];  // bf16 codebook [n][k]
__device__ __align__(16) float g_halfc2[8192];             // 0.5*|c_n|^2 exact fp32
__device__ int g_candc[N_NODES * 12];                      // 12 candidates/node (cb c)
__device__ int g_cands[N_NODES * 12];                      // 12 candidates/node (cb s)
__device__ int g_idxc[N_NODES], g_idxs[N_NODES];           // final exact indices
__device__ int g_counts[NG];
__device__ double g_loss[2];

// ---------------- helpers ----------------
__device__ __forceinline__ uint32_t smem_u32(const void* p) {
    uint32_t a;
    asm("{ .reg .u64 t; cvta.to.shared.u64 t, %1; cvt.u32.u64 %0, t; }" : "=r"(a) : "l"(p));
    return a;
}
__device__ __forceinline__ uint32_t pack_bf16x2(float a, float b) {
    uint32_t r;
    asm("cvt.rn.satfinite.bf16x2.f32 %0, %1, %2;" : "=r"(r) : "f"(b), "f"(a));
    return r;
}
__device__ __forceinline__ void mma_bf16(float* c, const uint32_t* a, uint32_t b0, uint32_t b1) {
    asm volatile(
        "mma.sync.aligned.m16n8k16.row.col.f32.bf16.bf16.f32 "
        "{%0,%1,%2,%3}, {%4,%5,%6,%7}, {%8,%9}, {%0,%1,%2,%3};"
        : "+f"(c[0]), "+f"(c[1]), "+f"(c[2]), "+f"(c[3])
        : "r"(a[0]), "r"(a[1]), "r"(a[2]), "r"(a[3]), "r"(b0), "r"(b1));
}
__device__ __forceinline__ void ldm4(uint32_t* r, uint32_t addr) {
    asm volatile("ldmatrix.sync.aligned.m8n8.x4.shared.b16 {%0,%1,%2,%3}, [%4];"
                 : "=r"(r[0]), "=r"(r[1]), "=r"(r[2]), "=r"(r[3]) : "r"(addr));
}
// top-3 (smallest) tracker, approx phase (tie-break irrelevant: exact rescore later)
__device__ __forceinline__ void upd3(float d, int idx, float (&bd)[3], int (&bi)[3]) {
    if (d < bd[2]) {
        if (d < bd[1]) {
            if (d < bd[0]) {
                bd[2] = bd[1]; bi[2] = bi[1];
                bd[1] = bd[0]; bi[1] = bi[0];
                bd[0] = d;     bi[0] = idx;
            } else {
                bd[2] = bd[1]; bi[2] = bi[1];
                bd[1] = d;     bi[1] = idx;
            }
        } else { bd[2] = d; bi[2] = idx; }
    }
}

// ---------- B prep (fused with init) ----------
__global__ void bprep_kernel(const float* __restrict__ cbc, const float* __restrict__ cbs,
                             float* __restrict__ out) {
    // fused init: blocks 0-255 zero CG/SG region, counts, losses
    if (blockIdx.x < 256) {
        int i = blockIdx.x * 256 + threadIdx.x;   // 0..65535
        if (i < NG) g_counts[i] = 0;
        if (i < 2) g_loss[i] = 0.0;
        out[OFF_CG + 2 * i] = 0.f;
        out[OFF_CG + 2 * i + 1] = 0.f;
    }
    int row = blockIdx.x * 8 + (threadIdx.x >> 5);
    int lane = threadIdx.x & 31;
    const float* src = (row < N_CODES) ? cbc + (size_t)row * EMB
                                       : cbs + (size_t)(row - N_CODES) * EMB;
    float4 v = ((const float4*)src)[lane];
    float ss = v.x * v.x + v.y * v.y + v.z * v.z + v.w * v.w;
    uint32_t* hid = (uint32_t*)g_Bhi;
    hid[row * 64 + lane * 2] = pack_bf16x2(v.x, v.y);
    hid[row * 64 + lane * 2 + 1] = pack_bf16x2(v.z, v.w);
    for (int o = 16; o; o >>= 1) ss += __shfl_xor_sync(0xffffffffu, ss, o);
    if (lane == 0) g_halfc2[row] = 0.5f * ss;
}

// ---------- tensor GEMM (1-pass bf16) + per-thread top-3 ----------
// grid 256 CTAs x 256 threads; each CTA owns 128 m-rows, scans 8192 codes
// in 128 chunks of 64. B double-buffered bf16 in smem, ldmatrix loads.
#define BSTRIDE 272
#define BUFB 17408                       // 64 rows * 272B
#define SMEM_GEMM (2 * BUFB + 512)       // 2x hi + 2x256B halfc2

__device__ __forceinline__ void prefetch(char* smem, int ci, int tid) {
    int buf = ci & 1;
    int nb = ci * 64;
    char* hid = smem + buf * BUFB;
#pragma unroll
    for (int i = 0; i < 4; i++) {
        int idx = tid + i * 256;                 // 0..1023
        int row = idx >> 4, seg = idx & 15;
        __pipeline_memcpy_async(hid + row * BSTRIDE + seg * 16,
                                (const char*)g_Bhi + (size_t)(nb + row) * 256 + seg * 16, 16);
    }
    if (tid < 16)
        __pipeline_memcpy_async(smem + 2 * BUFB + (ci & 1) * 256 + tid * 16,
                                (const char*)g_halfc2 + (size_t)nb * 4 + tid * 16, 16);
}

template <int CB>
__device__ __forceinline__ void half_loop(
    char* smem, uint32_t smemBase, uint32_t rp, int tid, int c,
    const uint32_t (&Ahi)[8][4], float g0, float g1,
    float (&d0)[3], int (&i0)[3], float (&d1)[3], int (&i1)[3]) {
    for (int i = 0; i < 64; i++) {
        int ci = CB * 64 + i;
        __pipeline_wait_prior(0);
        __syncthreads();
        if (ci + 1 < 128) { prefetch(smem, ci + 1, tid); __pipeline_commit(); }
        int buf = ci & 1;
        uint32_t hiB = smemBase + buf * BUFB + rp;
        const float* h2 = (const float*)(smem + 2 * BUFB + buf * 256);
        float acc[8][4];
#pragma unroll
        for (int t = 0; t < 8; t++)
#pragma unroll
            for (int j = 0; j < 4; j++) acc[t][j] = 0.f;
#pragma unroll
        for (int kt = 0; kt < 8; kt++) {
            uint32_t BH[4][4];
#pragma unroll
            for (int j = 0; j < 4; j++)
                ldm4(BH[j], hiB + j * (16 * BSTRIDE) + kt * 32);
#pragma unroll
            for (int t = 0; t < 8; t++)
                mma_bf16(acc[t], Ahi[kt],
                         BH[t >> 1][(t & 1) * 2], BH[t >> 1][(t & 1) * 2 + 1]);
        }
#pragma unroll
        for (int t = 0; t < 8; t++) {
            float2 hh = *(const float2*)(h2 + t * 8 + 2 * c);
            int col = i * 64 + t * 8 + 2 * c;       // local codebook index 0..4095
            upd3(fmaf(-g0, acc[t][0], hh.x), col, d0, i0);
            upd3(fmaf(-g0, acc[t][1], hh.y), col + 1, d0, i0);
            upd3(fmaf(-g1, acc[t][2], hh.x), col, d1, i1);
            upd3(fmaf(-g1, acc[t][3], hh.y), col + 1, d1, i1);
        }
    }
}

__global__ void __launch_bounds__(256)
gemm_argmin_kernel(const float* __restrict__ nodef, const float* __restrict__ score) {
    extern __shared__ char smem[];
    const int tid = threadIdx.x;
    const int w = tid >> 5, lane = tid & 31;
    const int gp = lane >> 2, c = lane & 3;
    const int mbase = blockIdx.x * 128;
    const int r0 = mbase + w * 16 + gp, r1 = r0 + 8;

    prefetch(smem, 0, tid);
    __pipeline_commit();

    // A fragments (bf16), loaded once per CTA
    uint32_t Ahi[8][4];
#pragma unroll
    for (int kt = 0; kt < 8; kt++) {
        const float* p0 = nodef + (size_t)r0 * EMB + kt * 16 + 2 * c;
        const float* p1 = nodef + (size_t)r1 * EMB + kt * 16 + 2 * c;
        float2 v;
        v = *(const float2*)p0;       Ahi[kt][0] = pack_bf16x2(v.x, v.y);
        v = *(const float2*)p1;       Ahi[kt][1] = pack_bf16x2(v.x, v.y);
        v = *(const float2*)(p0 + 8); Ahi[kt][2] = pack_bf16x2(v.x, v.y);
        v = *(const float2*)(p1 + 8); Ahi[kt][3] = pack_bf16x2(v.x, v.y);
    }

    float s0 = score[r0], s1 = score[r1];
    float gc0 = 0.5f + 0.5f * s0, gc1 = 0.5f + 0.5f * s1;
    float gs0 = 1.0f - 0.5f * s0, gs1 = 1.0f - 0.5f * s1;

    // ldmatrix per-thread row address part
    int g8 = lane >> 3, rr = lane & 7;
    uint32_t rp = (uint32_t)((8 * (g8 >> 1) + rr) * BSTRIDE + (g8 & 1) * 16);
    uint32_t smemBase = smem_u32(smem);

    const float INF = __int_as_float(0x7f800000);
    float dC0[3] = {INF, INF, INF}, dC1[3] = {INF, INF, INF};
    float dS0[3] = {INF, INF, INF}, dS1[3] = {INF, INF, INF};
    int iC0[3] = {0, 0, 0}, iC1[3] = {0, 0, 0}, iS0[3] = {0, 0, 0}, iS1[3] = {0, 0, 0};

    half_loop<0>(smem, smemBase, rp, tid, c, Ahi, gc0, gc1, dC0, iC0, dC1, iC1);
    half_loop<1>(smem, smemBase, rp, tid, c, Ahi, gs0, gs1, dS0, iS0, dS1, iS1);

    // each thread writes its 3 candidates per row per codebook (12 total per row/cb)
    int b0 = r0 * 12 + c * 3, b1 = r1 * 12 + c * 3;
#pragma unroll
    for (int j = 0; j < 3; j++) {
        g_candc[b0 + j] = iC0[j];
        g_candc[b1 + j] = iC1[j];
        g_cands[b0 + j] = iS0[j];
        g_cands[b1 + j] = iS1[j];
    }
}

// ---------- exact fp32 rescore of 12 candidates (batched loads + ILP reduce) ----------
__global__ void __launch_bounds__(64)
rescore_kernel(const float* __restrict__ nodef, const float* __restrict__ score,
               const float* __restrict__ cbc, const float* __restrict__ cbs) {
    int n = blockIdx.x;
    int wid = threadIdx.x >> 5, lane = threadIdx.x & 31;
    const int* cand = (wid ? g_cands : g_candc) + n * 12;
    const float* cb = wid ? cbs : cbc;
    const float* h2 = g_halfc2 + (wid ? 4096 : 0);
    float4 x = ((const float4*)(nodef + (size_t)n * EMB))[lane];

    int idx[12];
#pragma unroll
    for (int j = 0; j < 12; j++) idx[j] = cand[j];

    float4 av[12];
#pragma unroll
    for (int j = 0; j < 12; j++)
        av[j] = ((const float4*)(cb + (size_t)idx[j] * EMB))[lane];

    float pd[12];
#pragma unroll
    for (int j = 0; j < 12; j++)
        pd[j] = x.x * av[j].x + x.y * av[j].y + x.z * av[j].z + x.w * av[j].w;

#pragma unroll
    for (int o = 16; o; o >>= 1) {
#pragma unroll
        for (int j = 0; j < 12; j++)
            pd[j] += __shfl_xor_sync(0xffffffffu, pd[j], o);
    }

    if (lane == 0) {
        float s = score[n];
        float g = wid ? (1.0f - 0.5f * s) : (0.5f + 0.5f * s);
        float bestd = __int_as_float(0x7f800000);
        int besti = 0x7fffffff;
#pragma unroll
        for (int j = 0; j < 12; j++) {
            float D = fmaf(-g, pd[j], h2[idx[j]]);
            if (D < bestd || (D == bestd && idx[j] < besti)) { bestd = D; besti = idx[j]; }
        }
        if (wid) g_idxs[n] = besti; else g_idxc[n] = besti;
    }
}

// ---------- per-node outputs + segment sums + commit losses (fp32 accum) ----------
// grid 1024 blocks x 128 threads, 32 nodes per block
__global__ void __launch_bounds__(128)
node_kernel(const float* __restrict__ nodef, const float* __restrict__ score,
            const int* __restrict__ batch,
            const float* __restrict__ cbc, const float* __restrict__ cbs,
            float* __restrict__ out) {
    __shared__ float s_sh[32];
    __shared__ int b_sh[32], ic_sh[32], is_sh[32];
    __shared__ float lred[8];
    const int tid = threadIdx.x;
    const int n0 = blockIdx.x * 32;
    if (tid < 32) {
        int n = n0 + tid;
        s_sh[tid] = score[n];
        b_sh[tid] = batch[n];
        ic_sh[tid] = g_idxc[n];
        is_sh[tid] = g_idxs[n];
    }
    __syncthreads();
    float* csum = out + OFF_CG;
    float* ssum = out + OFF_SG;
    float* cn = out + OFF_CN;
    float* sn = out + OFF_SN;
    const int d = tid;
    float cacc = 0.f, sacc = 0.f;
    float lc = 0.f, ls = 0.f;                  // fp32 accumulation (64 squares/thread)
    int curg = b_sh[0], runlen = 0;
    for (int ii = 0; ii < 32; ii += 4) {
        float xv[4], qcv[4], qsv[4];
#pragma unroll
        for (int u = 0; u < 4; u++) {
            int n = n0 + ii + u;
            xv[u] = nodef[(size_t)n * EMB + d];
            qcv[u] = cbc[(size_t)ic_sh[ii + u] * EMB + d];
            qsv[u] = cbs[(size_t)is_sh[ii + u] * EMB + d];
        }
#pragma unroll
        for (int u = 0; u < 4; u++) {
            int i = ii + u;
            int n = n0 + i;
            int gidx = b_sh[i];
            if (gidx != curg) {
                atomicAdd(&csum[curg * EMB + d], cacc);
                atomicAdd(&ssum[curg * EMB + d], sacc);
                if (d == 0) atomicAdd(&g_counts[curg], runlen);
                cacc = 0.f; sacc = 0.f; runlen = 0; curg = gidx;
            }
            float x = xv[u];
            float s = s_sh[i];
            float qc = qcv[u];
            float qs = qsv[u];
            float cv = x * s + qc;
            float sv = x * (1.f - s) + qs;
            cn[(size_t)n * EMB + d] = cv;
            sn[(size_t)n * EMB + d] = sv;
            float dc = qc - (0.5f + 0.5f * s) * x;
            float ds = qs - (1.0f - 0.5f * s) * x;
            lc = fmaf(dc, dc, lc);
            ls = fmaf(ds, ds, ls);
            cacc += cv; sacc += sv; runlen++;
        }
    }
    atomicAdd(&csum[curg * EMB + d], cacc);
    atomicAdd(&ssum[curg * EMB + d], sacc);
    if (d == 0) atomicAdd(&g_counts[curg], runlen);
    for (int o = 16; o; o >>= 1) {
        lc += __shfl_xor_sync(0xffffffffu, lc, o);
        ls += __shfl_xor_sync(0xffffffffu, ls, o);
    }
    int w = tid >> 5, lane = tid & 31;
    if (lane == 0) { lred[w] = lc; lred[4 + w] = ls; }
    __syncthreads();
    if (tid == 0) {
        atomicAdd(&g_loss[0], (double)(lred[0] + lred[1] + lred[2] + lred[3]));
        atomicAdd(&g_loss[1], (double)(lred[4] + lred[5] + lred[6] + lred[7]));
    }
}

// ---------- fused finalize (means + losses) + classifier head ----------
__global__ void __launch_bounds__(256)
head_kernel(const float* __restrict__ w1, const float* __restrict__ b1,
            const float* __restrict__ gamma, const float* __restrict__ beta,
            const float* __restrict__ rmean, const float* __restrict__ rvar,
            const float* __restrict__ w2, const float* __restrict__ b2,
            float* __restrict__ out) {
    __shared__ float cg_s[128];
    __shared__ float red[256];
    int g = blockIdx.x, j = threadIdx.x;
    if (j < 128) {
        float cnt = fmaxf((float)g_counts[g], 1.0f);
        float cgv = out[OFF_CG + g * EMB + j] / cnt;
        out[OFF_CG + g * EMB + j] = cgv;
        out[OFF_SG + g * EMB + j] = out[OFF_SG + g * EMB + j] / cnt;
        cg_s[j] = cgv;
    }
    if (g == 0 && j == 0) {
        out[OFF_LC] = (float)(g_loss[0] / ((double)N_NODES * (double)EMB));
        out[OFF_LS] = (float)(g_loss[1] / ((double)N_NODES * (double)EMB));
    }
    __syncthreads();
    float acc = 0.f;
#pragma unroll 8
    for (int k = 0; k < 128; k++) acc = fmaf(cg_s[k], w1[k * 256 + j], acc);
    float h = acc + b1[j];
    h = (h - rmean[j]) * rsqrtf(rvar[j] + 1e-5f) * gamma[j] + beta[j];
    h = fmaxf(h, 0.f);
    red[j] = h * w2[j];
    __syncthreads();
    for (int o = 128; o; o >>= 1) {
        if (j < o) red[j] += red[j + o];
        __syncthreads();
    }
    if (j == 0) out[OFF_LOGIT + g] = red[0] + b2[0];
}

extern "C" void kernel_launch(void* const* d_in, const int* in_sizes, int n_in,
                              void* d_out, int out_size) {
    (void)in_sizes; (void)n_in; (void)out_size;
    const float* nodef = (const float*)d_in[0];
    const float* score = (const float*)d_in[1];
    const int* batch = (const int*)d_in[2];
    const float* cbc = (const float*)d_in[3];
    const float* cbs = (const float*)d_in[4];
    const float* w1 = (const float*)d_in[5];
    const float* b1 = (const float*)d_in[6];
    const float* gamma = (const float*)d_in[7];
    const float* beta = (const float*)d_in[8];
    const float* rmean = (const float*)d_in[9];
    const float* rvar = (const float*)d_in[10];
    const float* w2 = (const float*)d_in[11];
    const float* b2 = (const float*)d_in[12];
    float* out = (float*)d_out;

    cudaFuncSetAttribute(gemm_argmin_kernel,
                         cudaFuncAttributeMaxDynamicSharedMemorySize, SMEM_GEMM);

    bprep_kernel<<<1024, 256>>>(cbc, cbs, out);
    gemm_argmin_kernel<<<256, 256, SMEM_GEMM>>>(nodef, score);
    rescore_kernel<<<N_NODES, 64>>>(nodef, score, cbc, cbs);
    node_kernel<<<1024, 128>>>(nodef, score, batch, cbc, cbs, out);
    head_kernel<<<NG, 256>>>(w1, b1, gamma, beta, rmean, rvar, w2, b2, out);
}

// round 16
// speedup vs baseline: 1.6541x; 1.0168x over previous
#include <cuda_runtime.h>
#include <cuda_pipeline.h>
#include <cuda_bf16.h>
#include <cstdint>

#define N_NODES 32768
#define EMB 128
#define N_CODES 4096
#define NG 512

// output layout: c_logit[512], c_graph[512*128], s_graph[512*128],
// loss_c, loss_s, c_node[32768*128], s_node[32768*128]
#define OFF_LOGIT 0
#define OFF_CG    512
#define OFF_SG    (512 + 65536)
#define OFF_LC    (512 + 2 * 65536)
#define OFF_LS    (OFF_LC + 1)
#define OFF_CN    (OFF_LS + 1)
#define OFF_SN    (OFF_CN + N_NODES * EMB)

// margin for exact-rescore pruning: must exceed 2x the worst-case bf16
// dot error (~2*0.5). Candidates with approx dist > min + MARGIN cannot
// be the exact argmin.
#define MARGIN 1.5f

// device scratch (no allocations allowed)
__device__ __align__(16) __nv_bfloat16 g_Bhi[8192 * 128];  // bf16 codebook [n][k]
__device__ __align__(16) float g_halfc2[8192];             // 0.5*|c_n|^2 exact fp32
__device__ int g_candc[N_NODES * 12];                      // 12 candidates/node (cb c)
__device__ int g_cands[N_NODES * 12];                      // 12 candidates/node (cb s)
__device__ float g_canddc[N_NODES * 12];                   // approx dists (cb c)
__device__ float g_candds[N_NODES * 12];                   // approx dists (cb s)
__device__ int g_idxc[N_NODES], g_idxs[N_NODES];           // final exact indices
__device__ int g_counts[NG];
__device__ double g_loss[2];

// ---------------- helpers ----------------
__device__ __forceinline__ uint32_t smem_u32(const void* p) {
    uint32_t a;
    asm("{ .reg .u64 t; cvta.to.shared.u64 t, %1; cvt.u32.u64 %0, t; }" : "=r"(a) : "l"(p));
    return a;
}
__device__ __forceinline__ uint32_t pack_bf16x2(float a, float b) {
    uint32_t r;
    asm("cvt.rn.satfinite.bf16x2.f32 %0, %1, %2;" : "=r"(r) : "f"(b), "f"(a));
    return r;
}
__device__ __forceinline__ void mma_bf16(float* c, const uint32_t* a, uint32_t b0, uint32_t b1) {
    asm volatile(
        "mma.sync.aligned.m16n8k16.row.col.f32.bf16.bf16.f32 "
        "{%0,%1,%2,%3}, {%4,%5,%6,%7}, {%8,%9}, {%0,%1,%2,%3};"
        : "+f"(c[0]), "+f"(c[1]), "+f"(c[2]), "+f"(c[3])
        : "r"(a[0]), "r"(a[1]), "r"(a[2]), "r"(a[3]), "r"(b0), "r"(b1));
}
__device__ __forceinline__ void ldm4(uint32_t* r, uint32_t addr) {
    asm volatile("ldmatrix.sync.aligned.m8n8.x4.shared.b16 {%0,%1,%2,%3}, [%4];"
                 : "=r"(r[0]), "=r"(r[1]), "=r"(r[2]), "=r"(r[3]) : "r"(addr));
}
// top-3 (smallest) tracker, approx phase (tie-break irrelevant: exact rescore later)
__device__ __forceinline__ void upd3(float d, int idx, float (&bd)[3], int (&bi)[3]) {
    if (d < bd[2]) {
        if (d < bd[1]) {
            if (d < bd[0]) {
                bd[2] = bd[1]; bi[2] = bi[1];
                bd[1] = bd[0]; bi[1] = bi[0];
                bd[0] = d;     bi[0] = idx;
            } else {
                bd[2] = bd[1]; bi[2] = bi[1];
                bd[1] = d;     bi[1] = idx;
            }
        } else { bd[2] = d; bi[2] = idx; }
    }
}

// ---------- B prep (fused with init) ----------
__global__ void bprep_kernel(const float* __restrict__ cbc, const float* __restrict__ cbs,
                             float* __restrict__ out) {
    // fused init: blocks 0-255 zero CG/SG region, counts, losses
    if (blockIdx.x < 256) {
        int i = blockIdx.x * 256 + threadIdx.x;   // 0..65535
        if (i < NG) g_counts[i] = 0;
        if (i < 2) g_loss[i] = 0.0;
        out[OFF_CG + 2 * i] = 0.f;
        out[OFF_CG + 2 * i + 1] = 0.f;
    }
    int row = blockIdx.x * 8 + (threadIdx.x >> 5);
    int lane = threadIdx.x & 31;
    const float* src = (row < N_CODES) ? cbc + (size_t)row * EMB
                                       : cbs + (size_t)(row - N_CODES) * EMB;
    float4 v = ((const float4*)src)[lane];
    float ss = v.x * v.x + v.y * v.y + v.z * v.z + v.w * v.w;
    uint32_t* hid = (uint32_t*)g_Bhi;
    hid[row * 64 + lane * 2] = pack_bf16x2(v.x, v.y);
    hid[row * 64 + lane * 2 + 1] = pack_bf16x2(v.z, v.w);
    for (int o = 16; o; o >>= 1) ss += __shfl_xor_sync(0xffffffffu, ss, o);
    if (lane == 0) g_halfc2[row] = 0.5f * ss;
}

// ---------- tensor GEMM (1-pass bf16) + per-thread top-3 ----------
// grid 256 CTAs x 256 threads; each CTA owns 128 m-rows, scans 8192 codes
// in 128 chunks of 64. B double-buffered bf16 in smem, ldmatrix loads.
#define BSTRIDE 272
#define BUFB 17408                       // 64 rows * 272B
#define SMEM_GEMM (2 * BUFB + 512)       // 2x hi + 2x256B halfc2

__device__ __forceinline__ void prefetch(char* smem, int ci, int tid) {
    int buf = ci & 1;
    int nb = ci * 64;
    char* hid = smem + buf * BUFB;
#pragma unroll
    for (int i = 0; i < 4; i++) {
        int idx = tid + i * 256;                 // 0..1023
        int row = idx >> 4, seg = idx & 15;
        __pipeline_memcpy_async(hid + row * BSTRIDE + seg * 16,
                                (const char*)g_Bhi + (size_t)(nb + row) * 256 + seg * 16, 16);
    }
    if (tid < 16)
        __pipeline_memcpy_async(smem + 2 * BUFB + (ci & 1) * 256 + tid * 16,
                                (const char*)g_halfc2 + (size_t)nb * 4 + tid * 16, 16);
}

template <int CB>
__device__ __forceinline__ void half_loop(
    char* smem, uint32_t smemBase, uint32_t rp, int tid, int c,
    const uint32_t (&Ahi)[8][4], float g0, float g1,
    float (&d0)[3], int (&i0)[3], float (&d1)[3], int (&i1)[3]) {
    for (int i = 0; i < 64; i++) {
        int ci = CB * 64 + i;
        __pipeline_wait_prior(0);
        __syncthreads();
        if (ci + 1 < 128) { prefetch(smem, ci + 1, tid); __pipeline_commit(); }
        int buf = ci & 1;
        uint32_t hiB = smemBase + buf * BUFB + rp;
        const float* h2 = (const float*)(smem + 2 * BUFB + buf * 256);
        float acc[8][4];
#pragma unroll
        for (int t = 0; t < 8; t++)
#pragma unroll
            for (int j = 0; j < 4; j++) acc[t][j] = 0.f;
#pragma unroll
        for (int kt = 0; kt < 8; kt++) {
            uint32_t BH[4][4];
#pragma unroll
            for (int j = 0; j < 4; j++)
                ldm4(BH[j], hiB + j * (16 * BSTRIDE) + kt * 32);
#pragma unroll
            for (int t = 0; t < 8; t++)
                mma_bf16(acc[t], Ahi[kt],
                         BH[t >> 1][(t & 1) * 2], BH[t >> 1][(t & 1) * 2 + 1]);
        }
#pragma unroll
        for (int t = 0; t < 8; t++) {
            float2 hh = *(const float2*)(h2 + t * 8 + 2 * c);
            int col = i * 64 + t * 8 + 2 * c;       // local codebook index 0..4095
            upd3(fmaf(-g0, acc[t][0], hh.x), col, d0, i0);
            upd3(fmaf(-g0, acc[t][1], hh.y), col + 1, d0, i0);
            upd3(fmaf(-g1, acc[t][2], hh.x), col, d1, i1);
            upd3(fmaf(-g1, acc[t][3], hh.y), col + 1, d1, i1);
        }
    }
}

__global__ void __launch_bounds__(256)
gemm_argmin_kernel(const float* __restrict__ nodef, const float* __restrict__ score) {
    extern __shared__ char smem[];
    const int tid = threadIdx.x;
    const int w = tid >> 5, lane = tid & 31;
    const int gp = lane >> 2, c = lane & 3;
    const int mbase = blockIdx.x * 128;
    const int r0 = mbase + w * 16 + gp, r1 = r0 + 8;

    prefetch(smem, 0, tid);
    __pipeline_commit();

    // A fragments (bf16), loaded once per CTA
    uint32_t Ahi[8][4];
#pragma unroll
    for (int kt = 0; kt < 8; kt++) {
        const float* p0 = nodef + (size_t)r0 * EMB + kt * 16 + 2 * c;
        const float* p1 = nodef + (size_t)r1 * EMB + kt * 16 + 2 * c;
        float2 v;
        v = *(const float2*)p0;       Ahi[kt][0] = pack_bf16x2(v.x, v.y);
        v = *(const float2*)p1;       Ahi[kt][1] = pack_bf16x2(v.x, v.y);
        v = *(const float2*)(p0 + 8); Ahi[kt][2] = pack_bf16x2(v.x, v.y);
        v = *(const float2*)(p1 + 8); Ahi[kt][3] = pack_bf16x2(v.x, v.y);
    }

    float s0 = score[r0], s1 = score[r1];
    float gc0 = 0.5f + 0.5f * s0, gc1 = 0.5f + 0.5f * s1;
    float gs0 = 1.0f - 0.5f * s0, gs1 = 1.0f - 0.5f * s1;

    // ldmatrix per-thread row address part
    int g8 = lane >> 3, rr = lane & 7;
    uint32_t rp = (uint32_t)((8 * (g8 >> 1) + rr) * BSTRIDE + (g8 & 1) * 16);
    uint32_t smemBase = smem_u32(smem);

    const float INF = __int_as_float(0x7f800000);
    float dC0[3] = {INF, INF, INF}, dC1[3] = {INF, INF, INF};
    float dS0[3] = {INF, INF, INF}, dS1[3] = {INF, INF, INF};
    int iC0[3] = {0, 0, 0}, iC1[3] = {0, 0, 0}, iS0[3] = {0, 0, 0}, iS1[3] = {0, 0, 0};

    half_loop<0>(smem, smemBase, rp, tid, c, Ahi, gc0, gc1, dC0, iC0, dC1, iC1);
    half_loop<1>(smem, smemBase, rp, tid, c, Ahi, gs0, gs1, dS0, iS0, dS1, iS1);

    // each thread writes its 3 candidates (+ approx dists) per row per codebook
    int b0 = r0 * 12 + c * 3, b1 = r1 * 12 + c * 3;
#pragma unroll
    for (int j = 0; j < 3; j++) {
        g_candc[b0 + j] = iC0[j];
        g_candc[b1 + j] = iC1[j];
        g_cands[b0 + j] = iS0[j];
        g_cands[b1 + j] = iS1[j];
        g_canddc[b0 + j] = dC0[j];
        g_canddc[b1 + j] = dC1[j];
        g_candds[b0 + j] = dS0[j];
        g_candds[b1 + j] = dS1[j];
    }
}

// ---------- margin-pruned exact fp32 rescore ----------
// Only candidates with approx dist <= min + MARGIN can be the exact argmin
// (MARGIN >= 2x worst-case bf16 dot error). Typically ~1.3 candidates pass.
__global__ void __launch_bounds__(64)
rescore_kernel(const float* __restrict__ nodef, const float* __restrict__ score,
               const float* __restrict__ cbc, const float* __restrict__ cbs) {
    int n = blockIdx.x;
    int wid = threadIdx.x >> 5, lane = threadIdx.x & 31;
    const int* cand = (wid ? g_cands : g_candc) + n * 12;
    const float* cd = (wid ? g_candds : g_canddc) + n * 12;
    const float* cb = wid ? cbs : cbc;
    const float* h2 = g_halfc2 + (wid ? 4096 : 0);

    // all lanes load the same 12 (idx, dist) pairs -> warp-uniform filter
    int idx[12];
    float da[12];
    float dmin = __int_as_float(0x7f800000);
#pragma unroll
    for (int j = 0; j < 12; j++) {
        idx[j] = cand[j];
        da[j] = cd[j];
        dmin = fminf(dmin, da[j]);
    }
    float thr = dmin + MARGIN;

    float4 x = ((const float4*)(nodef + (size_t)n * EMB))[lane];
    float s = score[n];
    float g = wid ? (1.0f - 0.5f * s) : (0.5f + 0.5f * s);

    float bestd = __int_as_float(0x7f800000);
    int besti = 0x7fffffff;
#pragma unroll
    for (int j = 0; j < 12; j++) {
        if (da[j] <= thr) {   // warp-uniform branch
            float4 a = ((const float4*)(cb + (size_t)idx[j] * EMB))[lane];
            float d = x.x * a.x + x.y * a.y + x.z * a.z + x.w * a.w;
#pragma unroll
            for (int o = 16; o; o >>= 1) d += __shfl_xor_sync(0xffffffffu, d, o);
            float D = fmaf(-g, d, h2[idx[j]]);
            if (D < bestd || (D == bestd && idx[j] < besti)) { bestd = D; besti = idx[j]; }
        }
    }
    if (lane == 0) {
        if (wid) g_idxs[n] = besti; else g_idxc[n] = besti;
    }
}

// ---------- per-node outputs + segment sums + commit losses (fp32 accum) ----------
// grid 1024 blocks x 128 threads, 32 nodes per block
__global__ void __launch_bounds__(128)
node_kernel(const float* __restrict__ nodef, const float* __restrict__ score,
            const int* __restrict__ batch,
            const float* __restrict__ cbc, const float* __restrict__ cbs,
            float* __restrict__ out) {
    __shared__ float s_sh[32];
    __shared__ int b_sh[32], ic_sh[32], is_sh[32];
    __shared__ float lred[8];
    const int tid = threadIdx.x;
    const int n0 = blockIdx.x * 32;
    if (tid < 32) {
        int n = n0 + tid;
        s_sh[tid] = score[n];
        b_sh[tid] = batch[n];
        ic_sh[tid] = g_idxc[n];
        is_sh[tid] = g_idxs[n];
    }
    __syncthreads();
    float* csum = out + OFF_CG;
    float* ssum = out + OFF_SG;
    float* cn = out + OFF_CN;
    float* sn = out + OFF_SN;
    const int d = tid;
    float cacc = 0.f, sacc = 0.f;
    float lc = 0.f, ls = 0.f;                  // fp32 accumulation (64 squares/thread)
    int curg = b_sh[0], runlen = 0;
    for (int ii = 0; ii < 32; ii += 4) {
        float xv[4], qcv[4], qsv[4];
#pragma unroll
        for (int u = 0; u < 4; u++) {
            int n = n0 + ii + u;
            xv[u] = nodef[(size_t)n * EMB + d];
            qcv[u] = cbc[(size_t)ic_sh[ii + u] * EMB + d];
            qsv[u] = cbs[(size_t)is_sh[ii + u] * EMB + d];
        }
#pragma unroll
        for (int u = 0; u < 4; u++) {
            int i = ii + u;
            int n = n0 + i;
            int gidx = b_sh[i];
            if (gidx != curg) {
                atomicAdd(&csum[curg * EMB + d], cacc);
                atomicAdd(&ssum[curg * EMB + d], sacc);
                if (d == 0) atomicAdd(&g_counts[curg], runlen);
                cacc = 0.f; sacc = 0.f; runlen = 0; curg = gidx;
            }
            float x = xv[u];
            float s = s_sh[i];
            float qc = qcv[u];
            float qs = qsv[u];
            float cv = x * s + qc;
            float sv = x * (1.f - s) + qs;
            cn[(size_t)n * EMB + d] = cv;
            sn[(size_t)n * EMB + d] = sv;
            float dc = qc - (0.5f + 0.5f * s) * x;
            float ds = qs - (1.0f - 0.5f * s) * x;
            lc = fmaf(dc, dc, lc);
            ls = fmaf(ds, ds, ls);
            cacc += cv; sacc += sv; runlen++;
        }
    }
    atomicAdd(&csum[curg * EMB + d], cacc);
    atomicAdd(&ssum[curg * EMB + d], sacc);
    if (d == 0) atomicAdd(&g_counts[curg], runlen);
    for (int o = 16; o; o >>= 1) {
        lc += __shfl_xor_sync(0xffffffffu, lc, o);
        ls += __shfl_xor_sync(0xffffffffu, ls, o);
    }
    int w = tid >> 5, lane = tid & 31;
    if (lane == 0) { lred[w] = lc; lred[4 + w] = ls; }
    __syncthreads();
    if (tid == 0) {
        atomicAdd(&g_loss[0], (double)(lred[0] + lred[1] + lred[2] + lred[3]));
        atomicAdd(&g_loss[1], (double)(lred[4] + lred[5] + lred[6] + lred[7]));
    }
}

// ---------- fused finalize (means + losses) + classifier head ----------
__global__ void __launch_bounds__(256)
head_kernel(const float* __restrict__ w1, const float* __restrict__ b1,
            const float* __restrict__ gamma, const float* __restrict__ beta,
            const float* __restrict__ rmean, const float* __restrict__ rvar,
            const float* __restrict__ w2, const float* __restrict__ b2,
            float* __restrict__ out) {
    __shared__ float cg_s[128];
    __shared__ float red[256];
    int g = blockIdx.x, j = threadIdx.x;
    if (j < 128) {
        float cnt = fmaxf((float)g_counts[g], 1.0f);
        float cgv = out[OFF_CG + g * EMB + j] / cnt;
        out[OFF_CG + g * EMB + j] = cgv;
        out[OFF_SG + g * EMB + j] = out[OFF_SG + g * EMB + j] / cnt;
        cg_s[j] = cgv;
    }
    if (g == 0 && j == 0) {
        out[OFF_LC] = (float)(g_loss[0] / ((double)N_NODES * (double)EMB));
        out[OFF_LS] = (float)(g_loss[1] / ((double)N_NODES * (double)EMB));
    }
    __syncthreads();
    float acc = 0.f;
#pragma unroll 8
    for (int k = 0; k < 128; k++) acc = fmaf(cg_s[k], w1[k * 256 + j], acc);
    float h = acc + b1[j];
    h = (h - rmean[j]) * rsqrtf(rvar[j] + 1e-5f) * gamma[j] + beta[j];
    h = fmaxf(h, 0.f);
    red[j] = h * w2[j];
    __syncthreads();
    for (int o = 128; o; o >>= 1) {
        if (j < o) red[j] += red[j + o];
        __syncthreads();
    }
    if (j == 0) out[OFF_LOGIT + g] = red[0] + b2[0];
}

extern "C" void kernel_launch(void* const* d_in, const int* in_sizes, int n_in,
                              void* d_out, int out_size) {
    (void)in_sizes; (void)n_in; (void)out_size;
    const float* nodef = (const float*)d_in[0];
    const float* score = (const float*)d_in[1];
    const int* batch = (const int*)d_in[2];
    const float* cbc = (const float*)d_in[3];
    const float* cbs = (const float*)d_in[4];
    const float* w1 = (const float*)d_in[5];
    const float* b1 = (const float*)d_in[6];
    const float* gamma = (const float*)d_in[7];
    const float* beta = (const float*)d_in[8];
    const float* rmean = (const float*)d_in[9];
    const float* rvar = (const float*)d_in[10];
    const float* w2 = (const float*)d_in[11];
    const float* b2 = (const float*)d_in[12];
    float* out = (float*)d_out;

    cudaFuncSetAttribute(gemm_argmin_kernel,
                         cudaFuncAttributeMaxDynamicSharedMemorySize, SMEM_GEMM);

    bprep_kernel<<<1024, 256>>>(cbc, cbs, out);
    gemm_argmin_kernel<<<256, 256, SMEM_GEMM>>>(nodef, score);
    rescore_kernel<<<N_NODES, 64>>>(nodef, score, cbc, cbs);
    node_kernel<<<1024, 128>>>(nodef, score, batch, cbc, cbs, out);
    head_kernel<<<NG, 256>>>(w1, b1, gamma, beta, rmean, rvar, w2, b2, out);
}